// round 6
// baseline (speedup 1.0000x reference)
#include <cuda_runtime.h>
#include <cstdint>

#define B_ 8
#define V_ 8192
#define N_ 2048
#define C_ 128
#define GRID_ 128
#define THR_ 512

typedef unsigned long long ull;

// ---------- f32x2 helpers (sm_100+ packed fp32: SASS FFMA2) ----------
__device__ __forceinline__ ull pk2(float lo, float hi) {
    ull r; asm("mov.b64 %0, {%1, %2};" : "=l"(r) : "f"(lo), "f"(hi)); return r;
}
__device__ __forceinline__ void upk2(ull v, float& lo, float& hi) {
    asm("mov.b64 {%0, %1}, %2;" : "=f"(lo), "=f"(hi) : "l"(v));
}
__device__ __forceinline__ ull ffma2(ull a, ull b, ull c) {
    ull d; asm("fma.rn.f32x2 %0, %1, %2, %3;" : "=l"(d) : "l"(a), "l"(b), "l"(c)); return d;
}

// ---------- device scratch ----------
__device__ float g_buf[B_ * N_];            // g[b,n]
__device__ float cand_val[4 * B_ * V_];     // per n-chunk exact best d2
__device__ int   cand_idx[4 * B_ * V_];     // per n-chunk best index
__device__ unsigned int bar1, bar2, bar_done;

__device__ __forceinline__ void grid_barrier(unsigned int* ctr, int t) {
    __threadfence();
    __syncthreads();
    if (t == 0) {
        atomicAdd(ctr, 1u);
        while (*(volatile unsigned int*)ctr < GRID_) __nanosleep(64);
    }
    __syncthreads();
    __threadfence();
}

// =====================================================================
// ONE persistent kernel, grid=128 (1 CTA/SM), 512 threads, 96KB smem.
//
// Phase 1: g table. Block: 128 rows (2x64). 2D warp tile: warp covers
//   16 rows x 32 d (lane = lr:4 x ld:8, thread 4r x 4d) -> W smem reads
//   span only 256B/instr (was 1KB) and x reads are paired LDS.128.
// Phase 2: argmin partials. Block=(b:8|vq:4|nq:4): 2048 verts (Q=4/thr),
//   512 points pair-packed in smem. 2 LDS.128 per point-pair amortized
//   over 4 vertices (12 FFMA2) -> L1TEX off the critical path.
//   Screen best-2 segments, exact reference-rounding rescan, store cand.
// Phase 3: combine 4 chunks ascending (first-occurrence) + gather g.
// =====================================================================
__global__ void __launch_bounds__(THR_, 1)
kernelFused(const float* __restrict__ verts,
            const float* __restrict__ gpos,
            const float* __restrict__ processed,
            const float* __restrict__ W1,
            const float* __restrict__ b1,
            const float* __restrict__ W2,
            const float* __restrict__ b2,
            float* __restrict__ out) {
    extern __shared__ char sm[];
    ull*   Ws  = (ull*)sm;                    // phase1 packed W1: 64KB
    float* Xs  = (float*)(sm + 65536);        // phase1 X tile: 32KB
    float* pts = (float*)sm;                  // phase2 points: 8KB (alias)
    __shared__ float red[64][33];

    const int t   = threadIdx.x;
    const int bid = blockIdx.x;

    // ---------------- Phase 1: g table ----------------
    // Pack W1 -> smem: Ws[c2*64 + d/2 pairs]: Ws[c2*128/2...]: layout
    // Wsv index c2*64 + d2 holds {W1[2c2][2d2],W1[2c2][2d2+1]}? No:
    // keep K-packed: Ws[c2*128 + d] = {W1[2c2][d], W1[2c2+1][d]}
#pragma unroll
    for (int k = 0; k < 16; k++) {
        int i = t + k * THR_;                 // 0..8191
        int c2 = i >> 7, d = i & 127;
        Ws[i] = pk2(W1[(2 * c2) * C_ + d], W1[(2 * c2 + 1) * C_ + d]);
    }

    const int lane = t & 31;
    const int wid  = t >> 5;
    const int lr = lane >> 3;                 // 0..3
    const int ld = lane & 7;                  // 0..7
    const int wr = wid >> 2;                  // 0..3
    const int wd = wid & 3;                   // 0..3
    const int r0 = wr * 16 + lr * 4;          // 4 rows
    const int d0 = wd * 32 + ld * 4;          // 4 outputs
    const ulonglong2* Wsv = (const ulonglong2*)Ws;

#pragma unroll 1
    for (int h = 0; h < 2; h++) {
        const int rb = bid * 128 + h * 64;

        const float4* src = (const float4*)(processed + (size_t)rb * C_);
        float4* dst = (float4*)Xs;
#pragma unroll
        for (int k = 0; k < 4; k++) dst[t + k * THR_] = src[t + k * THR_];
        __syncthreads();

        ull acc[4][4];
#pragma unroll
        for (int i = 0; i < 4; i++)
#pragma unroll
            for (int j = 0; j < 4; j++) acc[i][j] = 0ull;

#pragma unroll 4
        for (int c4 = 0; c4 < 32; c4++) {     // two c2 per step
            // x: one LDS.128 per row covers c2 = 2c4 and 2c4+1
            ull xa[4], xb[4];
#pragma unroll
            for (int i = 0; i < 4; i++) {
                ulonglong2 xv = *(const ulonglong2*)&Xs[(r0 + i) * 128 + 4 * c4];
                xa[i] = xv.x; xb[i] = xv.y;
            }
#pragma unroll
            for (int half = 0; half < 2; half++) {
                int c2 = 2 * c4 + half;
                ulonglong2 wa = Wsv[c2 * 64 + (d0 >> 1)];
                ulonglong2 wb = Wsv[c2 * 64 + (d0 >> 1) + 1];
                ull w2[4] = {wa.x, wa.y, wb.x, wb.y};
#pragma unroll
                for (int i = 0; i < 4; i++) {
                    ull xi = half ? xb[i] : xa[i];
#pragma unroll
                    for (int j = 0; j < 4; j++)
                        acc[i][j] = ffma2(xi, w2[j], acc[i][j]);
                }
            }
        }

        float part[4] = {0.f, 0.f, 0.f, 0.f};
#pragma unroll
        for (int j = 0; j < 4; j++) {
            float b1j = b1[d0 + j];
            float w2j = W2[d0 + j];
#pragma unroll
            for (int i = 0; i < 4; i++) {
                float lo, hi; upk2(acc[i][j], lo, hi);
                float hv = fmaxf(lo + hi + b1j, 0.f);
                part[i] = fmaf(hv, w2j, part[i]);
            }
        }
#pragma unroll
        for (int i = 0; i < 4; i++) red[r0 + i][wd * 8 + ld] = part[i];
        __syncthreads();

        if (t < 64) {
            float s = b2[0];
#pragma unroll
            for (int k = 0; k < 32; k++) s += red[t][k];
            g_buf[rb + t] = s;
        }
        __syncthreads();
    }

    grid_barrier(&bar1, t);

    // ---------------- Phase 2: argmin partials ----------------
    const int nq = bid & 3;
    const int vq = (bid >> 2) & 3;
    const int b  = bid >> 4;
    const int n0 = nq * 512;
    const int v0 = vq * 2048;

    // Pair-packed 512-point tile: pair j -> {x0,x1,y0,y1}{z0,z1,pp0,pp1}
    if (t < 256) {
        const float* p0 = gpos + ((size_t)b * N_ + n0 + 2 * t) * 3;
        float x0 = p0[0], y0 = p0[1], z0 = p0[2];
        float x1 = p0[3], y1 = p0[4], z1 = p0[5];
        float pp0 = __fmaf_rn(z0, z0, __fmaf_rn(y0, y0, __fmul_rn(x0, x0)));
        float pp1 = __fmaf_rn(z1, z1, __fmaf_rn(y1, y1, __fmul_rn(x1, x1)));
        float4* d = (float4*)&pts[t * 8];
        d[0] = make_float4(x0, x1, y0, y1);
        d[1] = make_float4(z0, z1, pp0, pp1);
    }
    __syncthreads();

    // 4 vertices per thread: v0 + t + q*512
    float nvx[4], nvy[4], nvz[4], vvq[4];
    ull Xp[4], Yp[4], Zp[4];
#pragma unroll
    for (int q = 0; q < 4; q++) {
        const float* vp = verts + ((size_t)b * V_ + v0 + q * 512 + t) * 3;
        float x = vp[0], y = vp[1], z = vp[2];
        nvx[q] = -2.f * x; nvy[q] = -2.f * y; nvz[q] = -2.f * z;
        vvq[q] = __fmaf_rn(z, z, __fmaf_rn(y, y, __fmul_rn(x, x)));
        Xp[q] = pk2(nvx[q], nvx[q]);
        Yp[q] = pk2(nvy[q], nvy[q]);
        Zp[q] = pk2(nvz[q], nvz[q]);
    }

    const float INF = __int_as_float(0x7f800000);
    float best[4] = {INF, INF, INF, INF};
    float sec [4] = {INF, INF, INF, INF};
    int sgA[4] = {0, 0, 0, 0};
    int sgB[4] = {0, 0, 0, 0};

    // 16 segments of 32 points (16 pairs)
    for (int s = 0; s < 16; s++) {
        float m[4] = {INF, INF, INF, INF};
        const ulonglong2* base = (const ulonglong2*)&pts[s * 128];
#pragma unroll 4
        for (int k = 0; k < 16; k++) {
            ulonglong2 a  = base[2 * k];       // {x0,x1},{y0,y1}
            ulonglong2 bq = base[2 * k + 1];   // {z0,z1},{pp0,pp1}
#pragma unroll
            for (int q = 0; q < 4; q++) {
                ull sc = ffma2(Zp[q], bq.x,
                          ffma2(Yp[q], a.y,
                           ffma2(Xp[q], a.x, bq.y)));
                float lo, hi; upk2(sc, lo, hi);
                m[q] = fminf(m[q], fminf(lo, hi));
            }
        }
#pragma unroll
        for (int q = 0; q < 4; q++) {
            if (m[q] < best[q]) { sec[q] = best[q]; sgB[q] = sgA[q];
                                  best[q] = m[q];   sgA[q] = s; }
            else if (m[q] < sec[q]) { sec[q] = m[q]; sgB[q] = s; }
        }
    }

    // Exact rescan (reference rounding: mul,fma,fma,add,add), ascending
#pragma unroll 1
    for (int q = 0; q < 4; q++) {
        int lo = min(sgA[q], sgB[q]);
        int hi = max(sgA[q], sgB[q]);
        float cur = INF;
        int idx = 0;
#pragma unroll 1
        for (int pass = 0; pass < 2; pass++) {
            if (pass == 1 && hi == lo) break;
            int sb = (pass == 0 ? lo : hi) * 32;
#pragma unroll 1
            for (int i = 0; i < 32; i++) {
                int p = sb + i;
                const float* qp = &pts[(p >> 1) * 8 + (p & 1)];
                float s2 = __fmaf_rn(nvz[q], qp[4],
                            __fmaf_rn(nvy[q], qp[2],
                             __fmul_rn(nvx[q], qp[0])));
                float d2 = __fadd_rn(__fadd_rn(vvq[q], s2), qp[6]);
                if (d2 < cur) { cur = d2; idx = p; }
            }
        }
        int o = b * V_ + v0 + q * 512 + t;
        cand_val[nq * (B_ * V_) + o] = cur;
        cand_idx[nq * (B_ * V_) + o] = n0 + idx;
    }

    grid_barrier(&bar2, t);

    // ---------------- Phase 3: combine + gather ----------------
    {
        int i = bid * THR_ + t;               // 0..65535
        float bv = cand_val[i];
        int   bi = cand_idx[i];
#pragma unroll
        for (int c = 1; c < 4; c++) {
            float v = cand_val[c * (B_ * V_) + i];
            int   x = cand_idx[c * (B_ * V_) + i];
            if (v < bv) { bv = v; bi = x; }
        }
        out[i] = g_buf[(i >> 13) * N_ + bi];
    }

    // ---------------- Exit: reset barriers (last block) ----------------
    __syncthreads();
    if (t == 0) {
        unsigned int r = atomicAdd(&bar_done, 1u);
        if (r == GRID_ - 1) {                 // strictly after ALL work
            atomicExch(&bar1, 0u);
            atomicExch(&bar2, 0u);
            atomicExch(&bar_done, 0u);
        }
    }
}

// =====================================================================
extern "C" void kernel_launch(void* const* d_in, const int* in_sizes, int n_in,
                              void* d_out, int out_size) {
    const float* verts = (const float*)d_in[0];   // [8,8192,3]
    const float* gpos  = (const float*)d_in[1];   // [8,2048,3]
    const float* proc  = (const float*)d_in[2];   // [8,2048,128]
    const float* W1    = (const float*)d_in[3];   // [128,128]
    const float* b1    = (const float*)d_in[4];   // [128]
    const float* W2    = (const float*)d_in[5];   // [128,1]
    const float* b2    = (const float*)d_in[6];   // [1]
    float* out = (float*)d_out;                   // [8,8192,1]

    cudaFuncSetAttribute(kernelFused, cudaFuncAttributeMaxDynamicSharedMemorySize,
                         96 * 1024);
    kernelFused<<<GRID_, THR_, 96 * 1024>>>(verts, gpos, proc, W1, b1, W2, b2, out);
}